// round 14
// baseline (speedup 1.0000x reference)
#include <cuda_runtime.h>
#include <cuda_fp16.h>
#include <cstdint>

namespace {

typedef unsigned int u32;

constexpr int AST = 44;                    // A smem row stride (words; 80 fp16 + pad)
constexpr int BST = 44;                    // B smem row stride (words)
constexpr int A_WORDS = 64 * AST;          // 2816 per buffer (x2)
constexpr int B_WORDS = 256 * BST;         // 11264 (single buffer)
constexpr int X_WORDS = 24 * 256;          // 6144: 8 ch x 3 rows x 256 px
constexpr int SMEM_TOTAL = (2 * A_WORDS + B_WORDS + X_WORDS) * 4;  // 92160 B

// Packed fp16 weights: row oc (64), 320 words = 640 fp16 k-cols.
// k-order: iter (8 ch) -> pass (4 ch) -> channel -> tap (0..8 conv, 9 = quad M).
__device__ u32 g_A[64 * 320];
__device__ float g_bias[64];

__device__ __forceinline__ void mma_f16(float* d, const u32* a, u32 b0, u32 b1) {
    asm volatile(
        "mma.sync.aligned.m16n8k16.row.col.f32.f16.f16.f32 "
        "{%0,%1,%2,%3}, {%4,%5,%6,%7}, {%8,%9}, {%0,%1,%2,%3};"
        : "+f"(d[0]), "+f"(d[1]), "+f"(d[2]), "+f"(d[3])
        : "r"(a[0]), "r"(a[1]), "r"(a[2]), "r"(a[3]), "r"(b0), "r"(b1));
}

__device__ __forceinline__ void ldmx4(u32* r, u32 addr) {
    asm volatile("ldmatrix.sync.aligned.m8n8.x4.shared.b16 {%0,%1,%2,%3}, [%4];"
                 : "=r"(r[0]), "=r"(r[1]), "=r"(r[2]), "=r"(r[3]) : "r"(addr));
}

__device__ __forceinline__ u32 smem_u32(const void* p) {
    u32 a;
    asm("{ .reg .u64 t; cvta.to.shared.u64 t, %1; cvt.u32.u64 %0, t; }" : "=r"(a) : "l"(p));
    return a;
}

__device__ __forceinline__ void cp_async16(u32 dst, const void* src) {
    asm volatile("cp.async.cg.shared.global [%0], [%1], 16;"
                 :: "r"(dst), "l"(src) : "memory");
}

// pack two f32 -> fp16x2 word (lo = a, hi = b)
__device__ __forceinline__ u32 h2pack(float a, float b) {
    u32 d;
    asm("cvt.rn.f16x2.f32 %0, %1, %2;" : "=r"(d) : "f"(b), "f"(a));
    return d;
}

// grid 64 (channel i) x 256 threads (64 oc x 4 q-slices)
__global__ void precompute_kernel(const float* __restrict__ lw,
                                  const float* __restrict__ lb,
                                  const float* __restrict__ w2aw,
                                  const float* __restrict__ w2ab,
                                  const float* __restrict__ w2bw,
                                  const float* __restrict__ w2bb) {
    const int i = blockIdx.x;
    const int o = (int)threadIdx.x & 63;
    const int qq = (int)threadIdx.x >> 6;
    __shared__ float red[4][64];

    {
        const float* wb = w2bw + qq * 4096 + o * 64;
        const float* wa = w2aw + qq * 4096 + i;
        float m = 0.f;
#pragma unroll 8
        for (int mm = 0; mm < 64; mm++) m = fmaf(wb[mm], wa[mm * 64], m);
        red[qq][o] = m;
    }
    __syncthreads();

    if (qq == 0) {
        float w[10];
#pragma unroll
        for (int t = 0; t < 9; t++) w[t] = lw[(o * 64 + i) * 9 + t];
        w[9] = ((red[0][o] + red[1][o]) + (red[2][o] + red[3][o]));  // Sn tap

        // word base: iter*40 + pass*20 + chp*5
        const int wbase = o * 320 + (i >> 3) * 40 + (((i >> 2) & 1) * 20) + (i & 3) * 5;
#pragma unroll
        for (int j = 0; j < 5; j++)
            g_A[wbase + j] = h2pack(w[2 * j], w[2 * j + 1]);

        if (i == 0) {
            float c = 0.f;
            for (int q = 0; q < 4; q++) {
                const float* wb = w2bw + q * 4096 + o * 64;
                const float* ab = w2ab + q * 64;
                float hh = 0.f;
#pragma unroll 8
                for (int mm = 0; mm < 64; mm++) hh = fmaf(wb[mm], ab[mm], hh);
                c += hh + w2bb[q * 64 + o];
            }
            g_bias[o] = lb[o] + c;
        }
    }
}

// Build fp16 features for 8 channels (2 passes of 4) from the staged X tile.
// Pass p writes bytes [p*80, p*80+79] of Bs[cx] = 5 aligned uint4. (R13 verified)
__device__ __forceinline__ void build_B(u32* Bs, const float* Xs, int cx, int y) {
    const int xm1 = (cx - 1) & 255, xp1 = (cx + 1) & 255;
#pragma unroll
    for (int p = 0; p < 2; p++) {
        u32 fv[20];
#pragma unroll
        for (int c2 = 0; c2 < 4; c2++) {
            const float* xr = Xs + ((p * 4 + c2) * 3) * 256;
            float v[9];
#pragma unroll
            for (int r = 0; r < 3; r++) {
                v[r * 3 + 0] = xr[r * 256 + xm1];
                v[r * 3 + 1] = xr[r * 256 + cx];
                v[r * 3 + 2] = xr[r * 256 + xp1];
            }

            float s = ((v[0] + v[1]) + (v[2] + v[3])) +
                      ((v[4] + v[5]) + (v[6] + v[7])) + v[8];
            float s2 = v[0] * v[0];
#pragma unroll
            for (int t = 1; t < 9; t++) s2 = fmaf(v[t], v[t], s2);
            const float Sn = fmaf(s, s, s2) * (1.0f / 90.0f);

            float f[10];
#pragma unroll
            for (int t = 0; t < 9; t++) f[t] = v[t];
            // zero-pad masks (conv taps only; Sn stays circular)
            if (y == 0)    { f[0] = 0.f; f[1] = 0.f; f[2] = 0.f; }
            if (y == 255)  { f[6] = 0.f; f[7] = 0.f; f[8] = 0.f; }
            if (cx == 0)   { f[0] = 0.f; f[3] = 0.f; f[6] = 0.f; }
            if (cx == 255) { f[2] = 0.f; f[5] = 0.f; f[8] = 0.f; }
            f[9] = Sn;
#pragma unroll
            for (int j = 0; j < 5; j++)
                fv[c2 * 5 + j] = h2pack(f[2 * j], f[2 * j + 1]);
        }
        u32* bp = Bs + cx * BST + p * 20;
#pragma unroll
        for (int j = 0; j < 5; j++)
            *(uint4*)(bp + j * 4) =
                make_uint4(fv[4 * j], fv[4 * j + 1], fv[4 * j + 2], fv[4 * j + 3]);
    }
}

// 2048 CTAs (blockIdx.x = b*256 + y), 128 threads (4 warps), 2 CTAs/SM.
// Warp w owns output tile oc[0..63] x px[w*64..w*64+63] (acc 4m x 8n x 4; R10 mapping).
// Each thread builds 2 pixels (tid, tid+128). fp16 m16n8k16; 8 iters x 8 channels.
// Smem: A double buffer, B single buffer, X stage (8ch x 3 circular rows).
__global__ __launch_bounds__(128, 2)
void volterra_hmma(const float* __restrict__ x, float* __restrict__ out) {
    extern __shared__ u32 smem[];
    const u32 As_b = smem_u32(smem);                 // + buf*A_WORDS*4
    u32* Bs = smem + 2 * A_WORDS;
    float* Xs = (float*)(smem + 2 * A_WORDS + B_WORDS);
    const u32 Bs_b = As_b + 2 * A_WORDS * 4;
    const u32 Xs_b = Bs_b + B_WORDS * 4;

    const int tid = (int)threadIdx.x;
    const int w = tid >> 5;       // 0..3
    const int lane = tid & 31;
    const int b = (int)blockIdx.x >> 8;
    const int y = (int)blockIdx.x & 255;
    const int cx0 = tid;
    const int cx1 = tid + 128;

    const float* xb = x + ((size_t)b << 22);

    // ldmatrix lane-role
    const int lrow = lane & 15;
    const int lcol = (lane >> 4) * 4;

    float acc[4][8][4];
#pragma unroll
    for (int m = 0; m < 4; m++)
#pragma unroll
        for (int n = 0; n < 8; n++)
#pragma unroll
            for (int r = 0; r < 4; r++) acc[m][n][r] = 0.f;

    // A-stage roles: 640 quads over 128 threads, exactly 5 passes
    int aq_off[5], aq_src[5];
#pragma unroll
    for (int p = 0; p < 5; p++) {
        int idx = tid + p * 128;
        int oc = idx / 10, j = idx - oc * 10;
        aq_off[p] = (oc * AST + j * 4) << 2;
        aq_src[p] = oc * 320 + j * 4;       // + iter*40
    }
    // X-stage roles: 1536 quads over 128 threads, exactly 12 passes
    u32 xq_dst[12];
    int xq_src[12];
    {
        const int rowoff[3] = { ((y - 1) & 255) << 8, y << 8, ((y + 1) & 255) << 8 };
#pragma unroll
        for (int p = 0; p < 12; p++) {
            int idx = tid + p * 128;
            int rowIdx = idx >> 6, chunk = idx & 63;
            int c = rowIdx / 3, r = rowIdx - c * 3;
            xq_dst[p] = Xs_b + (u32)(((rowIdx << 8) + chunk * 4) << 2);
            xq_src[p] = c * 65536 + rowoff[r] + chunk * 4;  // + iter*8 ch via base ptr
        }
    }

    // prologue: stage A(0) + X(0), then build B(0)
#pragma unroll
    for (int p = 0; p < 5; p++)
        cp_async16(As_b + (u32)aq_off[p], g_A + aq_src[p]);
#pragma unroll
    for (int p = 0; p < 12; p++)
        cp_async16(xq_dst[p], xb + xq_src[p]);
    asm volatile("cp.async.commit_group;" ::: "memory");
    asm volatile("cp.async.wait_group 0;" ::: "memory");
    __syncthreads();
    build_B(Bs, Xs, cx0, y);
    build_B(Bs, Xs, cx1, y);

#pragma unroll 1
    for (int iter = 0; iter < 8; iter++) {
        const int buf = iter & 1;
        const int nbuf = buf ^ 1;

        __syncthreads();  // build(iter) STS visible everywhere

        // stage A(iter+1) + X(iter+1) (overlaps MMA below)
        if (iter < 7) {
            const u32* gAn = g_A + (iter + 1) * 40;
            const u32 abase = As_b + (u32)(nbuf * A_WORDS * 4);
            const float* xn = xb + ((size_t)((iter + 1) * 8) << 16);
#pragma unroll
            for (int p = 0; p < 5; p++)
                cp_async16(abase + (u32)aq_off[p], gAn + aq_src[p]);
#pragma unroll
            for (int p = 0; p < 12; p++)
                cp_async16(xq_dst[p], xn + xq_src[p]);
        }
        asm volatile("cp.async.commit_group;" ::: "memory");

        // ---- MMA(iter): 5 k16-steps, 64x64 warp tile ----
        const u32 Ab = As_b + (u32)(buf * A_WORDS * 4);
#pragma unroll
        for (int k5 = 0; k5 < 5; k5++) {
            u32 a[4][4];
#pragma unroll
            for (int m = 0; m < 4; m++)
                ldmx4(a[m], Ab + (u32)(((m * 16 + lrow) * AST + k5 * 8 + lcol) << 2));
#pragma unroll
            for (int np = 0; np < 4; np++) {
                u32 bb[4];
                ldmx4(bb, Bs_b + (u32)(((w * 64 + np * 16 + lrow) * BST + k5 * 8 + lcol) << 2));
#pragma unroll
                for (int m = 0; m < 4; m++) {
                    mma_f16(acc[m][2 * np + 0], a[m], bb[0], bb[2]);
                    mma_f16(acc[m][2 * np + 1], a[m], bb[1], bb[3]);
                }
            }
        }

        if (iter < 7) {
            asm volatile("cp.async.wait_group 0;" ::: "memory");
            __syncthreads();  // all MMA reads of B done; X(iter+1) landed
            build_B(Bs, Xs, cx0, y);  // write B(iter+1)
            build_B(Bs, Xs, cx1, y);
        }
    }

    // ---- epilogue: bias + float2 stores (fragment-native layout, R10-verified) ----
    const int r_ = lane >> 2, cc_ = lane & 3;
#pragma unroll
    for (int m = 0; m < 4; m++) {
        const int oc0 = m * 16 + r_;
        const int oc1 = oc0 + 8;
        const float bo0 = g_bias[oc0];
        const float bo1 = g_bias[oc1];
        float* p0 = out + (((size_t)(b * 64 + oc0)) << 16) + (y << 8) + w * 64 + cc_ * 2;
        float* p1 = out + (((size_t)(b * 64 + oc1)) << 16) + (y << 8) + w * 64 + cc_ * 2;
#pragma unroll
        for (int n = 0; n < 8; n++) {
            float2 s0 = make_float2(acc[m][n][0] + bo0, acc[m][n][1] + bo0);
            float2 s1 = make_float2(acc[m][n][2] + bo1, acc[m][n][3] + bo1);
            *(float2*)(p0 + n * 8) = s0;
            *(float2*)(p1 + n * 8) = s1;
        }
    }
}

}  // namespace

extern "C" void kernel_launch(void* const* d_in, const int* in_sizes, int n_in,
                              void* d_out, int out_size) {
    (void)in_sizes; (void)n_in; (void)out_size;
    const float* x    = (const float*)d_in[0];
    const float* lw   = (const float*)d_in[1];
    const float* lb   = (const float*)d_in[2];
    const float* w2aw = (const float*)d_in[3];
    const float* w2ab = (const float*)d_in[4];
    const float* w2bw = (const float*)d_in[5];
    const float* w2bb = (const float*)d_in[6];
    float* out = (float*)d_out;

    static int attr_set = 0;
    if (!attr_set) {
        cudaFuncSetAttribute(volterra_hmma,
                             cudaFuncAttributeMaxDynamicSharedMemorySize, SMEM_TOTAL);
        attr_set = 1;
    }
    precompute_kernel<<<64, 256>>>(lw, lb, w2aw, w2ab, w2bw, w2bb);
    volterra_hmma<<<2048, 128, SMEM_TOTAL>>>(x, out);
}

// round 15
// speedup vs baseline: 1.0423x; 1.0423x over previous
#include <cuda_runtime.h>
#include <cuda_fp16.h>
#include <cstdint>

namespace {

typedef unsigned int u32;

constexpr int AST = 44;                    // A smem row stride (words; 80 fp16 + pad)
constexpr int BST = 44;                    // B smem row stride (words)
constexpr int A_WORDS = 64 * AST;          // 2816 per buffer (x2)
constexpr int B_WORDS = 256 * BST;         // 11264 (single buffer)
constexpr int X_WORDS = 24 * 256;          // 6144: 8 ch x 3 rows x 256 px
constexpr int SMEM_TOTAL = (2 * A_WORDS + B_WORDS + X_WORDS) * 4;  // 92160 B

// Packed fp16 weights: row oc (64), 320 words = 640 fp16 k-cols.
// k-order: iter (8 ch) -> pass (4 ch) -> channel -> tap (0..8 conv, 9 = quad M).
__device__ u32 g_A[64 * 320];
__device__ float g_bias[64];

__device__ __forceinline__ void mma_f16(float* d, const u32* a, u32 b0, u32 b1) {
    asm volatile(
        "mma.sync.aligned.m16n8k16.row.col.f32.f16.f16.f32 "
        "{%0,%1,%2,%3}, {%4,%5,%6,%7}, {%8,%9}, {%0,%1,%2,%3};"
        : "+f"(d[0]), "+f"(d[1]), "+f"(d[2]), "+f"(d[3])
        : "r"(a[0]), "r"(a[1]), "r"(a[2]), "r"(a[3]), "r"(b0), "r"(b1));
}

__device__ __forceinline__ void ldmx4(u32* r, u32 addr) {
    asm volatile("ldmatrix.sync.aligned.m8n8.x4.shared.b16 {%0,%1,%2,%3}, [%4];"
                 : "=r"(r[0]), "=r"(r[1]), "=r"(r[2]), "=r"(r[3]) : "r"(addr));
}

__device__ __forceinline__ u32 smem_u32(const void* p) {
    u32 a;
    asm("{ .reg .u64 t; cvta.to.shared.u64 t, %1; cvt.u32.u64 %0, t; }" : "=r"(a) : "l"(p));
    return a;
}

__device__ __forceinline__ void cp_async16(u32 dst, const void* src) {
    asm volatile("cp.async.cg.shared.global [%0], [%1], 16;"
                 :: "r"(dst), "l"(src) : "memory");
}

// pack two f32 -> fp16x2 word (lo = a, hi = b)
__device__ __forceinline__ u32 h2pack(float a, float b) {
    u32 d;
    asm("cvt.rn.f16x2.f32 %0, %1, %2;" : "=r"(d) : "f"(b), "f"(a));
    return d;
}

// grid 64 (channel i) x 256 threads (64 oc x 4 q-slices)
__global__ void precompute_kernel(const float* __restrict__ lw,
                                  const float* __restrict__ lb,
                                  const float* __restrict__ w2aw,
                                  const float* __restrict__ w2ab,
                                  const float* __restrict__ w2bw,
                                  const float* __restrict__ w2bb) {
    const int i = blockIdx.x;
    const int o = (int)threadIdx.x & 63;
    const int qq = (int)threadIdx.x >> 6;
    __shared__ float red[4][64];

    {
        const float* wb = w2bw + qq * 4096 + o * 64;
        const float* wa = w2aw + qq * 4096 + i;
        float m = 0.f;
#pragma unroll 8
        for (int mm = 0; mm < 64; mm++) m = fmaf(wb[mm], wa[mm * 64], m);
        red[qq][o] = m;
    }
    __syncthreads();

    if (qq == 0) {
        float w[10];
#pragma unroll
        for (int t = 0; t < 9; t++) w[t] = lw[(o * 64 + i) * 9 + t];
        w[9] = ((red[0][o] + red[1][o]) + (red[2][o] + red[3][o]));  // Sn tap

        // word base: iter*40 + pass*20 + chp*5
        const int wbase = o * 320 + (i >> 3) * 40 + (((i >> 2) & 1) * 20) + (i & 3) * 5;
#pragma unroll
        for (int j = 0; j < 5; j++)
            g_A[wbase + j] = h2pack(w[2 * j], w[2 * j + 1]);

        if (i == 0) {
            float c = 0.f;
            for (int q = 0; q < 4; q++) {
                const float* wb = w2bw + q * 4096 + o * 64;
                const float* ab = w2ab + q * 64;
                float hh = 0.f;
#pragma unroll 8
                for (int mm = 0; mm < 64; mm++) hh = fmaf(wb[mm], ab[mm], hh);
                c += hh + w2bb[q * 64 + o];
            }
            g_bias[o] = lb[o] + c;
        }
    }
}

// Build fp16 features for 8 channels (2 passes of 4) from the staged X tile.
// Xm/Xc/Xp: per-thread base pointers (Xs + {xm1, cx, xp1}) -> immediate-offset LDS.
// mk[9]: precomputed zero-pad mask multipliers (conv taps; Sn stays circular).
__device__ __forceinline__ void build_B(u32* Bs, const float* Xm, const float* Xc,
                                        const float* Xp, int cx, const float* mk) {
#pragma unroll
    for (int p = 0; p < 2; p++) {
        u32 fv[20];
#pragma unroll
        for (int c2 = 0; c2 < 4; c2++) {
            const int base = ((p * 4 + c2) * 3) * 256;
            float v[9];
#pragma unroll
            for (int r = 0; r < 3; r++) {
                v[r * 3 + 0] = Xm[base + r * 256];
                v[r * 3 + 1] = Xc[base + r * 256];
                v[r * 3 + 2] = Xp[base + r * 256];
            }

            float s = ((v[0] + v[1]) + (v[2] + v[3])) +
                      ((v[4] + v[5]) + (v[6] + v[7])) + v[8];
            float s2 = v[0] * v[0];
#pragma unroll
            for (int t = 1; t < 9; t++) s2 = fmaf(v[t], v[t], s2);
            const float Sn = fmaf(s, s, s2) * (1.0f / 90.0f);

            float f[10];
#pragma unroll
            for (int t = 0; t < 9; t++) f[t] = v[t] * mk[t];
            f[9] = Sn;
#pragma unroll
            for (int j = 0; j < 5; j++)
                fv[c2 * 5 + j] = h2pack(f[2 * j], f[2 * j + 1]);
        }
        u32* bp = Bs + cx * BST + p * 20;
#pragma unroll
        for (int j = 0; j < 5; j++)
            *(uint4*)(bp + j * 4) =
                make_uint4(fv[4 * j], fv[4 * j + 1], fv[4 * j + 2], fv[4 * j + 3]);
    }
}

// 2048 CTAs (blockIdx.x = b*256 + y), 256 threads (8 warps), 2 CTAs/SM.
// Warp w owns output tile oc[0..63] x px[w*32..w*32+31]; fp16 m16n8k16.
// Smem: A double buffer, B single buffer, X stage (8ch x 3 circular rows).
// 8 iters x 8 channels. Body: sync; cp.async A/X(i+1); MMA(i); wait; sync; build(i+1).
__global__ __launch_bounds__(256, 2)
void volterra_hmma(const float* __restrict__ x, float* __restrict__ out) {
    extern __shared__ u32 smem[];
    const u32 As_b = smem_u32(smem);                 // + buf*A_WORDS*4
    u32* Bs = smem + 2 * A_WORDS;
    float* Xs = (float*)(smem + 2 * A_WORDS + B_WORDS);
    const u32 Bs_b = As_b + 2 * A_WORDS * 4;
    const u32 Xs_b = Bs_b + B_WORDS * 4;

    const int tid = (int)threadIdx.x;
    const int w = tid >> 5;
    const int lane = tid & 31;
    const int b = (int)blockIdx.x >> 8;
    const int y = (int)blockIdx.x & 255;
    const int cx = tid;
    const int xm1 = (cx - 1) & 255, xp1 = (cx + 1) & 255;

    const float* xb = x + ((size_t)b << 22);

    // per-thread build constants (hoisted out of all loops)
    const float* Xm = Xs + xm1;
    const float* Xc = Xs + cx;
    const float* Xp = Xs + xp1;
    const float cm0 = (cx != 0) ? 1.f : 0.f;
    const float cm2 = (cx != 255) ? 1.f : 0.f;
    const float rm0 = (y != 0) ? 1.f : 0.f;
    const float rm2 = (y != 255) ? 1.f : 0.f;
    const float mk[9] = { rm0 * cm0, rm0, rm0 * cm2,
                          cm0,       1.f, cm2,
                          rm2 * cm0, rm2, rm2 * cm2 };

    // ldmatrix lane-role
    const int lrow = lane & 15;
    const int lcol = (lane >> 4) * 4;

    float acc[4][4][4];
#pragma unroll
    for (int m = 0; m < 4; m++)
#pragma unroll
        for (int n = 0; n < 4; n++)
#pragma unroll
            for (int r = 0; r < 4; r++) acc[m][n][r] = 0.f;

    // A-stage roles: 640 quads over 256 threads, 3 passes
    int aq_off[3], aq_src[3];
#pragma unroll
    for (int p = 0; p < 3; p++) {
        int idx = tid + p * 256;
        int oc = idx / 10, j = idx - oc * 10;
        aq_off[p] = (oc * AST + j * 4) << 2;
        aq_src[p] = oc * 320 + j * 4;       // + iter*40
    }
    // X-stage roles: 1536 quads over 256 threads, 6 passes
    u32 xq_dst[6];
    int xq_src[6];
    {
        const int rowoff[3] = { ((y - 1) & 255) << 8, y << 8, ((y + 1) & 255) << 8 };
#pragma unroll
        for (int p = 0; p < 6; p++) {
            int idx = tid + p * 256;
            int rowIdx = idx >> 6, chunk = idx & 63;
            int c = rowIdx / 3, r = rowIdx - c * 3;
            xq_dst[p] = Xs_b + (u32)(((rowIdx << 8) + chunk * 4) << 2);
            xq_src[p] = c * 65536 + rowoff[r] + chunk * 4;  // + iter*8 ch via base ptr
        }
    }

    // prologue: stage A(0) + X(0), then build B(0)
#pragma unroll
    for (int p = 0; p < 3; p++) {
        if (tid + p * 256 < 640)
            cp_async16(As_b + (u32)aq_off[p], g_A + aq_src[p]);
    }
#pragma unroll
    for (int p = 0; p < 6; p++)
        cp_async16(xq_dst[p], xb + xq_src[p]);
    asm volatile("cp.async.commit_group;" ::: "memory");
    asm volatile("cp.async.wait_group 0;" ::: "memory");
    __syncthreads();
    build_B(Bs, Xm, Xc, Xp, cx, mk);

#pragma unroll 1
    for (int iter = 0; iter < 8; iter++) {
        const int buf = iter & 1;
        const int nbuf = buf ^ 1;

        __syncthreads();  // build(iter) STS visible everywhere

        // stage A(iter+1) + X(iter+1) (overlaps MMA below)
        if (iter < 7) {
            const u32* gAn = g_A + (iter + 1) * 40;
            const u32 abase = As_b + (u32)(nbuf * A_WORDS * 4);
            const float* xn = xb + ((size_t)((iter + 1) * 8) << 16);
#pragma unroll
            for (int p = 0; p < 3; p++) {
                if (tid + p * 256 < 640)
                    cp_async16(abase + (u32)aq_off[p], gAn + aq_src[p]);
            }
#pragma unroll
            for (int p = 0; p < 6; p++)
                cp_async16(xq_dst[p], xn + xq_src[p]);
        }
        asm volatile("cp.async.commit_group;" ::: "memory");

        // ---- MMA(iter): 5 k16-steps, fragments via ldmatrix.x4 ----
        const u32 Ab = As_b + (u32)(buf * A_WORDS * 4);
#pragma unroll
        for (int k5 = 0; k5 < 5; k5++) {
            u32 a[4][4];
#pragma unroll
            for (int m = 0; m < 4; m++)
                ldmx4(a[m], Ab + (u32)(((m * 16 + lrow) * AST + k5 * 8 + lcol) << 2));
#pragma unroll
            for (int np = 0; np < 2; np++) {
                u32 bb[4];
                ldmx4(bb, Bs_b + (u32)(((w * 32 + np * 16 + lrow) * BST + k5 * 8 + lcol) << 2));
#pragma unroll
                for (int m = 0; m < 4; m++) {
                    mma_f16(acc[m][2 * np + 0], a[m], bb[0], bb[2]);
                    mma_f16(acc[m][2 * np + 1], a[m], bb[1], bb[3]);
                }
            }
        }

        if (iter < 7) {
            asm volatile("cp.async.wait_group 0;" ::: "memory");
            __syncthreads();  // all MMA reads of B done; X(iter+1) landed
            build_B(Bs, Xm, Xc, Xp, cx, mk);  // write B(iter+1)
        }
    }

    // ---- epilogue: bias + float2 stores (fragment-native layout, verified) ----
    const int r_ = lane >> 2, cc_ = lane & 3;
#pragma unroll
    for (int m = 0; m < 4; m++) {
        const int oc0 = m * 16 + r_;
        const int oc1 = oc0 + 8;
        const float bo0 = g_bias[oc0];
        const float bo1 = g_bias[oc1];
        float* p0 = out + (((size_t)(b * 64 + oc0)) << 16) + (y << 8) + w * 32 + cc_ * 2;
        float* p1 = out + (((size_t)(b * 64 + oc1)) << 16) + (y << 8) + w * 32 + cc_ * 2;
#pragma unroll
        for (int n = 0; n < 4; n++) {
            float2 s0 = make_float2(acc[m][n][0] + bo0, acc[m][n][1] + bo0);
            float2 s1 = make_float2(acc[m][n][2] + bo1, acc[m][n][3] + bo1);
            *(float2*)(p0 + n * 8) = s0;
            *(float2*)(p1 + n * 8) = s1;
        }
    }
}

}  // namespace

extern "C" void kernel_launch(void* const* d_in, const int* in_sizes, int n_in,
                              void* d_out, int out_size) {
    (void)in_sizes; (void)n_in; (void)out_size;
    const float* x    = (const float*)d_in[0];
    const float* lw   = (const float*)d_in[1];
    const float* lb   = (const float*)d_in[2];
    const float* w2aw = (const float*)d_in[3];
    const float* w2ab = (const float*)d_in[4];
    const float* w2bw = (const float*)d_in[5];
    const float* w2bb = (const float*)d_in[6];
    float* out = (float*)d_out;

    static int attr_set = 0;
    if (!attr_set) {
        cudaFuncSetAttribute(volterra_hmma,
                             cudaFuncAttributeMaxDynamicSharedMemorySize, SMEM_TOTAL);
        attr_set = 1;
    }
    precompute_kernel<<<64, 256>>>(lw, lb, w2aw, w2ab, w2bw, w2bb);
    volterra_hmma<<<2048, 256, SMEM_TOTAL>>>(x, out);
}